// round 10
// baseline (speedup 1.0000x reference)
#include <cuda_runtime.h>
#include <cuda_bf16.h>
#include <cstdint>

#define T_LEN 64000
#define NB 4
#define CH 128
#define NCLS 256
#define CHUNK 32
#define NCHUNK 8
#define SPAN (CHUNK * NCHUNK)      // 256 t per CTA
#define NXCTA (T_LEN / SPAN)       // 250

// ---------------- static device buffers ----------------
__device__ unsigned short g_act0[(size_t)NB * 2 * T_LEN * CH];
__device__ unsigned short g_act1[(size_t)NB * 2 * T_LEN * CH];
__device__ uint32_t g_whi[27 * 2 * 128 * 64];
__device__ uint32_t g_wlo[27 * 2 * 128 * 64];
__device__ uint32_t g_wc[2 * 256 * 64];

// ---------------- helpers ----------------
__device__ __forceinline__ uint32_t smem_u32(const void* p) {
    uint32_t a;
    asm("{ .reg .u64 t; cvta.to.shared.u64 t, %1; cvt.u32.u64 %0, t; }" : "=r"(a) : "l"(p));
    return a;
}
__device__ __forceinline__ void cpa16(uint32_t dst, const void* src, int sz) {
    asm volatile("cp.async.cg.shared.global [%0], [%1], 16, %2;"
                 :: "r"(dst), "l"(src), "r"(sz) : "memory");
}
#define CP_COMMIT() asm volatile("cp.async.commit_group;" ::: "memory")
#define CP_WAIT1()  asm volatile("cp.async.wait_group 1;" ::: "memory")
#define CP_WAIT0()  asm volatile("cp.async.wait_group 0;" ::: "memory")

__device__ __forceinline__ void mma16816(float c[4], const uint32_t a[4],
                                         uint32_t b0, uint32_t b1) {
    asm volatile(
        "mma.sync.aligned.m16n8k16.row.col.f32.bf16.bf16.f32 "
        "{%0,%1,%2,%3}, {%4,%5,%6,%7}, {%8,%9}, {%0,%1,%2,%3};"
        : "+f"(c[0]), "+f"(c[1]), "+f"(c[2]), "+f"(c[3])
        : "r"(a[0]), "r"(a[1]), "r"(a[2]), "r"(a[3]), "r"(b0), "r"(b1));
}

// ---------------- prep: split + pack weights ----------------
__device__ __forceinline__ uint32_t pack_split(float w0, float w1, int plane) {
    __nv_bfloat16 h0 = __float2bfloat16(w0), h1 = __float2bfloat16(w1);
    if (plane == 0)
        return (uint32_t)__bfloat16_as_ushort(h0) |
               ((uint32_t)__bfloat16_as_ushort(h1) << 16);
    __nv_bfloat16 l0 = __float2bfloat16(w0 - __bfloat162float(h0));
    __nv_bfloat16 l1 = __float2bfloat16(w1 - __bfloat162float(h1));
    return (uint32_t)__bfloat16_as_ushort(l0) |
           ((uint32_t)__bfloat16_as_ushort(l1) << 16);
}

__global__ void prep_kernel(const float* __restrict__ wrest,
                            const float* __restrict__ wcls,
                            uint32_t* __restrict__ whi,
                            uint32_t* __restrict__ wlo,
                            uint32_t* __restrict__ wc) {
    int idx = blockIdx.x * blockDim.x + threadIdx.x;
    if (idx < 27 * 2 * 128 * 64) {
        int kp = idx & 63;
        int m = (idx >> 6) & 127;
        int tap = (idx >> 13) & 1;
        int L = idx >> 14;
        float w0 = wrest[((L * 128 + m) * 128 + kp * 2) * 2 + tap];
        float w1 = wrest[((L * 128 + m) * 128 + kp * 2 + 1) * 2 + tap];
        whi[idx] = pack_split(w0, w1, 0);
        wlo[idx] = pack_split(w0, w1, 1);
    }
    if (idx < 2 * 256 * 64) {
        int kp = idx & 63;
        int m = (idx >> 6) & 255;
        int pl = idx >> 14;
        float w0 = wcls[m * 128 + kp * 2];
        float w1 = wcls[m * 128 + kp * 2 + 1];
        wc[idx] = pack_split(w0, w1, pl);
    }
}

// ---------------- layer 0 ----------------
__global__ void layer0_kernel(const float* __restrict__ seq,
                              const float* __restrict__ wf,
                              unsigned short* __restrict__ actout) {
    int oc = threadIdx.x & 127;
    int half = threadIdx.x >> 7;
    int n = blockIdx.y;
    int t0 = blockIdx.x * 128 + half * 64;
    float w0 = wf[oc * 2], w1 = wf[oc * 2 + 1];
    const float* xs = seq + (size_t)n * T_LEN;
    unsigned short* ohi = actout + (size_t)(n * 2 + 0) * T_LEN * CH;
    unsigned short* olo = actout + (size_t)(n * 2 + 1) * T_LEN * CH;
    for (int j = 0; j < 64; j++) {
        int t = t0 + j;
        float x1 = xs[t];
        float x0 = (t >= 1) ? xs[t - 1] : 0.f;
        float y = fmaxf(w0 * x0 + w1 * x1, 0.f);
        __nv_bfloat16 h = __float2bfloat16(y);
        __nv_bfloat16 l = __float2bfloat16(y - __bfloat162float(h));
        ohi[(size_t)t * CH + oc] = __bfloat16_as_ushort(h);
        olo[(size_t)t * CH + oc] = __bfloat16_as_ushort(l);
    }
}

// ---------------- dilated-conv layer via mma.sync bf16 (512 threads) ----------------
// smem (u32 units):
//   [0, 34816)        W : [pl 2][tap 2][m 128][68]
//   [34816, 52224)    X : [buf 2][tile 4 = tap*2+plane][r 32][68]
//   [52224, 56576)    stage: u16[2 pl][32 t][136 m]
// 16 warps = 8(m of 16) x 2(n of 16). 3 independent accumulator sets.
__global__ void __launch_bounds__(512, 1) layer_mma(
    const unsigned short* __restrict__ actin,
    unsigned short* __restrict__ actout,
    const uint32_t* __restrict__ whi,
    const uint32_t* __restrict__ wlo, int d) {
    extern __shared__ uint32_t sm[];
    const uint32_t sb = smem_u32(sm);
    const int tid = threadIdx.x;
    const int lane = tid & 31, wid = tid >> 5;
    const int g = lane >> 2, tq = lane & 3;
    const int n = blockIdx.y;
    const int tbase = blockIdx.x * SPAN;
    const int m0 = (wid & 7) * 16;
    const int n0 = (wid >> 3) * 16;

    // ---- group 0: W (both planes) -> smem
#pragma unroll
    for (int i = 0; i < 16; i++) {
        int idx = i * 512 + tid;
        int row = idx >> 4, seg = idx & 15;   // row = pl*256 + tap*128 + m
        const uint32_t* src = ((row < 256) ? whi : wlo) + (row & 255) * 64 + seg * 4;
        cpa16(sb + (row * 68 + seg * 4) * 4, src, 16);
    }
    CP_COMMIT();

    auto load_x = [&](int c) {
        int buf = c & 1;
        int tcb = tbase + c * CHUNK;
#pragma unroll
        for (int i = 0; i < 4; i++) {
            int idx = i * 512 + tid;
            int tile = idx >> 9, rem = idx & 511;
            int r = rem >> 4, seg = rem & 15;
            int tap = tile >> 1, pl = tile & 1;
            int t = tcb + r - (tap == 0 ? d : 0);
            const unsigned short* src =
                actin + ((size_t)(n * 2 + pl) * T_LEN + (t < 0 ? 0 : t)) * CH + seg * 8;
            cpa16(sb + (34816 + buf * 8704 + tile * 2176 + r * 68 + seg * 4) * 4,
                  src, t >= 0 ? 16 : 0);
        }
        CP_COMMIT();
    };
    load_x(0);
    load_x(1);

    CP_WAIT1();
    __syncthreads();

    unsigned short* stg = (unsigned short*)(sm + 52224);

#pragma unroll 1
    for (int c = 0; c < NCHUNK; c++) {
        const int buf = c & 1;
        const uint32_t* X = sm + 34816 + buf * 8704;

        float acc[3][2][4];   // [product hh/hl/lh][nt][ci]
#pragma unroll
        for (int p = 0; p < 3; p++)
#pragma unroll
            for (int nt = 0; nt < 2; nt++)
#pragma unroll
                for (int j = 0; j < 4; j++) acc[p][nt][j] = 0.f;

#pragma unroll
        for (int tap = 0; tap < 2; tap++) {
            const uint32_t* Wh = sm + tap * 8704;
            const uint32_t* Wl = sm + 17408 + tap * 8704;
            const uint32_t* Xh = X + (tap * 2 + 0) * 2176;
            const uint32_t* Xl = X + (tap * 2 + 1) * 2176;
#pragma unroll
            for (int ks = 0; ks < 8; ks++) {
                uint32_t ah[4], al[4];
                uint32_t bh0[2], bh1[2], bl0[2], bl1[2];
                {
                    int r0 = (m0 + g) * 68, r1 = (m0 + g + 8) * 68;
                    ah[0] = Wh[r0 + ks * 8 + tq];
                    ah[1] = Wh[r1 + ks * 8 + tq];
                    ah[2] = Wh[r0 + ks * 8 + 4 + tq];
                    ah[3] = Wh[r1 + ks * 8 + 4 + tq];
                    al[0] = Wl[r0 + ks * 8 + tq];
                    al[1] = Wl[r1 + ks * 8 + tq];
                    al[2] = Wl[r0 + ks * 8 + 4 + tq];
                    al[3] = Wl[r1 + ks * 8 + 4 + tq];
                }
#pragma unroll
                for (int nt = 0; nt < 2; nt++) {
                    int xr = (n0 + nt * 8 + g) * 68;
                    bh0[nt] = Xh[xr + ks * 8 + tq];
                    bh1[nt] = Xh[xr + ks * 8 + 4 + tq];
                    bl0[nt] = Xl[xr + ks * 8 + tq];
                    bl1[nt] = Xl[xr + ks * 8 + 4 + tq];
                }
                // 6 independent MMAs
#pragma unroll
                for (int nt = 0; nt < 2; nt++)
                    mma16816(acc[0][nt], ah, bh0[nt], bh1[nt]);
#pragma unroll
                for (int nt = 0; nt < 2; nt++)
                    mma16816(acc[1][nt], ah, bl0[nt], bl1[nt]);
#pragma unroll
                for (int nt = 0; nt < 2; nt++)
                    mma16816(acc[2][nt], al, bh0[nt], bh1[nt]);
            }
        }

        __syncthreads();

        if (c + 2 < NCHUNK) load_x(c + 2);

        // -- epilogue: sum partials, relu + split into dedicated stage
#pragma unroll
        for (int nt = 0; nt < 2; nt++)
#pragma unroll
            for (int ci = 0; ci < 4; ci++) {
                int m = m0 + g + ((ci >> 1) * 8);
                int tl = n0 + nt * 8 + tq * 2 + (ci & 1);
                float y = acc[0][nt][ci] + acc[1][nt][ci] + acc[2][nt][ci];
                y = fmaxf(y, 0.f);
                __nv_bfloat16 h = __float2bfloat16(y);
                __nv_bfloat16 l = __float2bfloat16(y - __bfloat162float(h));
                stg[tl * 136 + m] = __bfloat16_as_ushort(h);
                stg[4352 + tl * 136 + m] = __bfloat16_as_ushort(l);
            }

        if (c + 1 < NCHUNK) {
            if (c + 2 < NCHUNK) CP_WAIT1();
            else CP_WAIT0();
        }
        __syncthreads();

        const int tcb = tbase + c * CHUNK;
#pragma unroll
        for (int i = 0; i < 2; i++) {
            int idx = i * 512 + tid;
            int pl = idx >> 9, rem = idx & 511;
            int r = rem >> 4, sg = rem & 15;
            uint4 v = *(const uint4*)(stg + pl * 4352 + r * 136 + sg * 8);
            *(uint4*)(actout + ((size_t)(n * 2 + pl) * T_LEN + tcb + r) * CH + sg * 8) = v;
        }
    }
}

// ---------------- classifier: 128 -> 256, + bias, no relu (256 threads) ----------------
__global__ void __launch_bounds__(256, 1) cls_mma(
    const unsigned short* __restrict__ actin,
    const uint32_t* __restrict__ wc,
    const float* __restrict__ bias,
    float* __restrict__ out) {
    extern __shared__ uint32_t sm[];
    const uint32_t sb = smem_u32(sm);
    const int tid = threadIdx.x;
    const int lane = tid & 31, wid = tid >> 5;
    const int g = lane >> 2, tq = lane & 3;
    const int n = blockIdx.y;
    const int tbase = blockIdx.x * SPAN;
    const int mz = blockIdx.z * 128;
    const int m0 = (wid & 3) * 32;
    const int n0 = (wid >> 2) * 16;

#pragma unroll
    for (int i = 0; i < 16; i++) {
        int idx = i * 256 + tid;
        int row = idx >> 4, seg = idx & 15;
        const uint32_t* src = wc + ((size_t)(row >> 7) * 256 + mz + (row & 127)) * 64 + seg * 4;
        cpa16(sb + (row * 68 + seg * 4) * 4, src, 16);
    }
    CP_COMMIT();

    auto load_x = [&](int c) {
        int buf = c & 1;
        int tcb = tbase + c * CHUNK;
#pragma unroll
        for (int i = 0; i < 4; i++) {
            int idx = i * 256 + tid;
            int pl = idx >> 9, rem = idx & 511;
            int r = rem >> 4, seg = rem & 15;
            const unsigned short* src =
                actin + ((size_t)(n * 2 + pl) * T_LEN + tcb + r) * CH + seg * 8;
            cpa16(sb + (17408 + buf * 4352 + pl * 2176 + r * 68 + seg * 4) * 4, src, 16);
        }
        CP_COMMIT();
    };
    load_x(0);
    load_x(1);
    CP_WAIT1();
    __syncthreads();

    float* stg = (float*)(sm + 26112);

#pragma unroll 1
    for (int c = 0; c < NCHUNK; c++) {
        const int buf = c & 1;
        const uint32_t* X = sm + 17408 + buf * 4352;

        float acc[3][2][2][4];
#pragma unroll
        for (int p = 0; p < 3; p++)
#pragma unroll
            for (int mt = 0; mt < 2; mt++)
#pragma unroll
                for (int nt = 0; nt < 2; nt++)
#pragma unroll
                    for (int j = 0; j < 4; j++) acc[p][mt][nt][j] = 0.f;

        const uint32_t* Wh = sm;
        const uint32_t* Wl = sm + 8704;
        const uint32_t* Xh = X;
        const uint32_t* Xl = X + 2176;
#pragma unroll
        for (int ks = 0; ks < 8; ks++) {
            uint32_t ah[2][4], al[2][4];
            uint32_t bh0[2], bh1[2], bl0[2], bl1[2];
#pragma unroll
            for (int mt = 0; mt < 2; mt++) {
                int r0 = (m0 + mt * 16 + g) * 68, r1 = (m0 + mt * 16 + g + 8) * 68;
                ah[mt][0] = Wh[r0 + ks * 8 + tq];
                ah[mt][1] = Wh[r1 + ks * 8 + tq];
                ah[mt][2] = Wh[r0 + ks * 8 + 4 + tq];
                ah[mt][3] = Wh[r1 + ks * 8 + 4 + tq];
                al[mt][0] = Wl[r0 + ks * 8 + tq];
                al[mt][1] = Wl[r1 + ks * 8 + tq];
                al[mt][2] = Wl[r0 + ks * 8 + 4 + tq];
                al[mt][3] = Wl[r1 + ks * 8 + 4 + tq];
            }
#pragma unroll
            for (int nt = 0; nt < 2; nt++) {
                int xr = (n0 + nt * 8 + g) * 68;
                bh0[nt] = Xh[xr + ks * 8 + tq];
                bh1[nt] = Xh[xr + ks * 8 + 4 + tq];
                bl0[nt] = Xl[xr + ks * 8 + tq];
                bl1[nt] = Xl[xr + ks * 8 + 4 + tq];
            }
#pragma unroll
            for (int mt = 0; mt < 2; mt++)
#pragma unroll
                for (int nt = 0; nt < 2; nt++)
                    mma16816(acc[0][mt][nt], ah[mt], bh0[nt], bh1[nt]);
#pragma unroll
            for (int mt = 0; mt < 2; mt++)
#pragma unroll
                for (int nt = 0; nt < 2; nt++)
                    mma16816(acc[1][mt][nt], ah[mt], bl0[nt], bl1[nt]);
#pragma unroll
            for (int mt = 0; mt < 2; mt++)
#pragma unroll
                for (int nt = 0; nt < 2; nt++)
                    mma16816(acc[2][mt][nt], al[mt], bh0[nt], bh1[nt]);
        }

        __syncthreads();
        if (c + 2 < NCHUNK) load_x(c + 2);

#pragma unroll
        for (int mt = 0; mt < 2; mt++)
#pragma unroll
            for (int nt = 0; nt < 2; nt++)
#pragma unroll
                for (int ci = 0; ci < 4; ci++) {
                    int m = m0 + mt * 16 + g + ((ci >> 1) * 8);
                    int tl = n0 + nt * 8 + tq * 2 + (ci & 1);
                    float y = acc[0][mt][nt][ci] + acc[1][mt][nt][ci] + acc[2][mt][nt][ci];
                    stg[m * 34 + tl] = y + __ldg(bias + mz + m);
                }

        if (c + 1 < NCHUNK) {
            if (c + 2 < NCHUNK) CP_WAIT1();
            else CP_WAIT0();
        }
        __syncthreads();

        const int tcb = tbase + c * CHUNK;
#pragma unroll
        for (int i = 0; i < 8; i++) {
            int idx = i * 256 + tid;
            int row = idx >> 4, sg = idx & 15;
            float2 v = *(const float2*)(stg + row * 34 + sg * 2);
            *(float2*)(out + ((size_t)n * NCLS + mz + row) * T_LEN + tcb + sg * 2) = v;
        }
    }
}

// ---------------- launch ----------------
extern "C" void kernel_launch(void* const* d_in, const int* in_sizes, int n_in,
                              void* d_out, int out_size) {
    (void)in_sizes; (void)n_in; (void)out_size;
    const float* seq     = (const float*)d_in[0];
    const float* w_first = (const float*)d_in[1];
    const float* w_rest  = (const float*)d_in[2];
    const float* w_cls   = (const float*)d_in[3];
    const float* b_cls   = (const float*)d_in[4];
    float* out = (float*)d_out;

    unsigned short *a0, *a1;
    uint32_t *whi, *wlo, *wc;
    cudaGetSymbolAddress((void**)&a0, g_act0);
    cudaGetSymbolAddress((void**)&a1, g_act1);
    cudaGetSymbolAddress((void**)&whi, g_whi);
    cudaGetSymbolAddress((void**)&wlo, g_wlo);
    cudaGetSymbolAddress((void**)&wc, g_wc);

    const int smem_layer = 56576 * 4;  // 226304 B
    const int smem_cls   = 30464 * 4;  // 121856 B
    cudaFuncSetAttribute(layer_mma, cudaFuncAttributeMaxDynamicSharedMemorySize, smem_layer);
    cudaFuncSetAttribute(cls_mma, cudaFuncAttributeMaxDynamicSharedMemorySize, smem_cls);

    prep_kernel<<<(27 * 2 * 128 * 64 + 255) / 256, 256>>>(w_rest, w_cls, whi, wlo, wc);
    layer0_kernel<<<dim3(T_LEN / 128, NB), 256>>>(seq, w_first, a0);

    for (int i = 1; i < 28; i++) {
        int l = i % 14;
        int d = 1 << (l % 10);
        const unsigned short* src = (i & 1) ? a0 : a1;
        unsigned short* dst       = (i & 1) ? a1 : a0;
        layer_mma<<<dim3(NXCTA, NB), 512, smem_layer>>>(
            src, dst, whi + (size_t)(i - 1) * 2 * 128 * 64,
            wlo + (size_t)(i - 1) * 2 * 128 * 64, d);
    }

    cls_mma<<<dim3(NXCTA, NB, 2), 256, smem_cls>>>(a1, wc, b_cls, out);
}

// round 11
// speedup vs baseline: 1.2066x; 1.2066x over previous
#include <cuda_runtime.h>
#include <cuda_bf16.h>
#include <cstdint>

#define T_LEN 64000
#define NB 4
#define CH 128
#define NCLS 256
#define CHUNK 64
#define NCHUNK 4
#define NITER 8                   // (chunk, tap) pairs
#define SPAN 256                  // t per CTA
#define NXCTA (T_LEN / SPAN)      // 250
// classifier
#define CCH 32
#define CNCH 8

// ---------------- static device buffers ----------------
__device__ unsigned short g_act0[(size_t)NB * 2 * T_LEN * CH];
__device__ unsigned short g_act1[(size_t)NB * 2 * T_LEN * CH];
__device__ uint32_t g_whi[27 * 2 * 128 * 64];
__device__ uint32_t g_wlo[27 * 2 * 128 * 64];
__device__ uint32_t g_wc[2 * 256 * 64];

// ---------------- helpers ----------------
__device__ __forceinline__ uint32_t smem_u32(const void* p) {
    uint32_t a;
    asm("{ .reg .u64 t; cvta.to.shared.u64 t, %1; cvt.u32.u64 %0, t; }" : "=r"(a) : "l"(p));
    return a;
}
__device__ __forceinline__ void cpa16(uint32_t dst, const void* src, int sz) {
    asm volatile("cp.async.cg.shared.global [%0], [%1], 16, %2;"
                 :: "r"(dst), "l"(src), "r"(sz) : "memory");
}
#define CP_COMMIT() asm volatile("cp.async.commit_group;" ::: "memory")
#define CP_WAIT1()  asm volatile("cp.async.wait_group 1;" ::: "memory")
#define CP_WAIT0()  asm volatile("cp.async.wait_group 0;" ::: "memory")

__device__ __forceinline__ void mma16816(float c[4], const uint32_t a[4],
                                         uint32_t b0, uint32_t b1) {
    asm volatile(
        "mma.sync.aligned.m16n8k16.row.col.f32.bf16.bf16.f32 "
        "{%0,%1,%2,%3}, {%4,%5,%6,%7}, {%8,%9}, {%0,%1,%2,%3};"
        : "+f"(c[0]), "+f"(c[1]), "+f"(c[2]), "+f"(c[3])
        : "r"(a[0]), "r"(a[1]), "r"(a[2]), "r"(a[3]), "r"(b0), "r"(b1));
}

// ---------------- prep: split + pack weights ----------------
__device__ __forceinline__ uint32_t pack_split(float w0, float w1, int plane) {
    __nv_bfloat16 h0 = __float2bfloat16(w0), h1 = __float2bfloat16(w1);
    if (plane == 0)
        return (uint32_t)__bfloat16_as_ushort(h0) |
               ((uint32_t)__bfloat16_as_ushort(h1) << 16);
    __nv_bfloat16 l0 = __float2bfloat16(w0 - __bfloat162float(h0));
    __nv_bfloat16 l1 = __float2bfloat16(w1 - __bfloat162float(h1));
    return (uint32_t)__bfloat16_as_ushort(l0) |
           ((uint32_t)__bfloat16_as_ushort(l1) << 16);
}

__global__ void prep_kernel(const float* __restrict__ wrest,
                            const float* __restrict__ wcls,
                            uint32_t* __restrict__ whi,
                            uint32_t* __restrict__ wlo,
                            uint32_t* __restrict__ wc) {
    int idx = blockIdx.x * blockDim.x + threadIdx.x;
    if (idx < 27 * 2 * 128 * 64) {
        int kp = idx & 63;
        int m = (idx >> 6) & 127;
        int tap = (idx >> 13) & 1;
        int L = idx >> 14;
        float w0 = wrest[((L * 128 + m) * 128 + kp * 2) * 2 + tap];
        float w1 = wrest[((L * 128 + m) * 128 + kp * 2 + 1) * 2 + tap];
        whi[idx] = pack_split(w0, w1, 0);
        wlo[idx] = pack_split(w0, w1, 1);
    }
    if (idx < 2 * 256 * 64) {
        int kp = idx & 63;
        int m = (idx >> 6) & 255;
        int pl = idx >> 14;
        float w0 = wcls[m * 128 + kp * 2];
        float w1 = wcls[m * 128 + kp * 2 + 1];
        wc[idx] = pack_split(w0, w1, pl);
    }
}

// ---------------- layer 0 ----------------
__global__ void layer0_kernel(const float* __restrict__ seq,
                              const float* __restrict__ wf,
                              unsigned short* __restrict__ actout) {
    int oc = threadIdx.x & 127;
    int half = threadIdx.x >> 7;
    int n = blockIdx.y;
    int t0 = blockIdx.x * 128 + half * 64;
    float w0 = wf[oc * 2], w1 = wf[oc * 2 + 1];
    const float* xs = seq + (size_t)n * T_LEN;
    unsigned short* ohi = actout + (size_t)(n * 2 + 0) * T_LEN * CH;
    unsigned short* olo = actout + (size_t)(n * 2 + 1) * T_LEN * CH;
    for (int j = 0; j < 64; j++) {
        int t = t0 + j;
        float x1 = xs[t];
        float x0 = (t >= 1) ? xs[t - 1] : 0.f;
        float y = fmaxf(w0 * x0 + w1 * x1, 0.f);
        __nv_bfloat16 h = __float2bfloat16(y);
        __nv_bfloat16 l = __float2bfloat16(y - __bfloat162float(h));
        ohi[(size_t)t * CH + oc] = __bfloat16_as_ushort(h);
        olo[(size_t)t * CH + oc] = __bfloat16_as_ushort(l);
    }
}

// ---------------- dilated-conv layer via mma.sync bf16 ----------------
// smem (u32 units):
//   [0, 34816)        W : [pl 2][tap 2][m 128][68]
//   [34816, 52224)    X : [buf 2][pl 2][r 64][68]    (buf = tap parity)
//   [52224, 56576)    stage: u16[2 pl][32 t][136 m]
// chunk = 64 t; 8 warps = 4(m of 32) x 2(n of 32); acc persists across taps.
__global__ void __launch_bounds__(256, 1) layer_mma(
    const unsigned short* __restrict__ actin,
    unsigned short* __restrict__ actout,
    const uint32_t* __restrict__ whi,
    const uint32_t* __restrict__ wlo, int d) {
    extern __shared__ uint32_t sm[];
    const uint32_t sb = smem_u32(sm);
    const int tid = threadIdx.x;
    const int lane = tid & 31, wid = tid >> 5;
    const int g = lane >> 2, tq = lane & 3;
    const int n = blockIdx.y;
    const int tbase = blockIdx.x * SPAN;
    const int m0 = (wid & 3) * 32;
    const int n0 = (wid >> 2) * 32;

    // ---- group: W (both planes) -> smem
#pragma unroll
    for (int i = 0; i < 32; i++) {
        int idx = i * 256 + tid;
        int row = idx >> 4, seg = idx & 15;   // row = pl*256 + tap*128 + m
        const uint32_t* src = ((row < 256) ? whi : wlo) + (row & 255) * 64 + seg * 4;
        cpa16(sb + (row * 68 + seg * 4) * 4, src, 16);
    }
    CP_COMMIT();

    // ---- per-(chunk,tap) X loader: 2 planes x 64 t
    auto load_xt = [&](int it) {
        int c = it >> 1, tap = it & 1, buf = it & 1;
        int tcb = tbase + c * CHUNK;
#pragma unroll
        for (int i = 0; i < 8; i++) {
            int idx = i * 256 + tid;          // 2048 segs
            int pl = idx >> 10, rem = idx & 1023;
            int r = rem >> 4, seg = rem & 15;
            int t = tcb + r - (tap == 0 ? d : 0);
            const unsigned short* src =
                actin + ((size_t)(n * 2 + pl) * T_LEN + (t < 0 ? 0 : t)) * CH + seg * 8;
            cpa16(sb + (34816 + buf * 8704 + pl * 4352 + r * 68 + seg * 4) * 4,
                  src, t >= 0 ? 16 : 0);
        }
        CP_COMMIT();
    };
    load_xt(0);
    load_xt(1);

    CP_WAIT1();          // W + iter0 complete (iter1 in flight)
    __syncthreads();

    unsigned short* stg = (unsigned short*)(sm + 52224);

    float acc[3][2][4][4];   // [product hh/hl/lh][mt][nt][ci]

#pragma unroll 1
    for (int it = 0; it < NITER; it++) {
        const int tap = it & 1, buf = it & 1;
        const uint32_t* Xb = sm + 34816 + buf * 8704;

        if (tap == 0) {
#pragma unroll
            for (int p = 0; p < 3; p++)
#pragma unroll
                for (int mt = 0; mt < 2; mt++)
#pragma unroll
                    for (int nt = 0; nt < 4; nt++)
#pragma unroll
                        for (int j = 0; j < 4; j++) acc[p][mt][nt][j] = 0.f;
        }

        const uint32_t* Wh = sm + tap * 8704;
        const uint32_t* Wl = sm + 17408 + tap * 8704;
        const uint32_t* Xh = Xb;
        const uint32_t* Xl = Xb + 4352;
#pragma unroll
        for (int ks = 0; ks < 8; ks++) {
            uint32_t ah[2][4], al[2][4];
            uint32_t bh0[4], bh1[4], bl0[4], bl1[4];
#pragma unroll
            for (int mt = 0; mt < 2; mt++) {
                int r0 = (m0 + mt * 16 + g) * 68, r1 = (m0 + mt * 16 + g + 8) * 68;
                ah[mt][0] = Wh[r0 + ks * 8 + tq];
                ah[mt][1] = Wh[r1 + ks * 8 + tq];
                ah[mt][2] = Wh[r0 + ks * 8 + 4 + tq];
                ah[mt][3] = Wh[r1 + ks * 8 + 4 + tq];
                al[mt][0] = Wl[r0 + ks * 8 + tq];
                al[mt][1] = Wl[r1 + ks * 8 + tq];
                al[mt][2] = Wl[r0 + ks * 8 + 4 + tq];
                al[mt][3] = Wl[r1 + ks * 8 + 4 + tq];
            }
#pragma unroll
            for (int nt = 0; nt < 4; nt++) {
                int xr = (n0 + nt * 8 + g) * 68;
                bh0[nt] = Xh[xr + ks * 8 + tq];
                bh1[nt] = Xh[xr + ks * 8 + 4 + tq];
                bl0[nt] = Xl[xr + ks * 8 + tq];
                bl1[nt] = Xl[xr + ks * 8 + 4 + tq];
            }
            // 24 independent MMAs
#pragma unroll
            for (int mt = 0; mt < 2; mt++)
#pragma unroll
                for (int nt = 0; nt < 4; nt++)
                    mma16816(acc[0][mt][nt], ah[mt], bh0[nt], bh1[nt]);
#pragma unroll
            for (int mt = 0; mt < 2; mt++)
#pragma unroll
                for (int nt = 0; nt < 4; nt++)
                    mma16816(acc[1][mt][nt], ah[mt], bl0[nt], bl1[nt]);
#pragma unroll
            for (int mt = 0; mt < 2; mt++)
#pragma unroll
                for (int nt = 0; nt < 4; nt++)
                    mma16816(acc[2][mt][nt], al[mt], bh0[nt], bh1[nt]);
        }

        __syncthreads();   // all warps done reading X[buf]; stage reads done

        if (it + 2 < NITER) load_xt(it + 2);

        if (tap == 1) {
            // epilogue for chunk c in two 32-t waves
            const int tcb = tbase + (it >> 1) * CHUNK;
#pragma unroll
            for (int h = 0; h < 2; h++) {
                if (n0 == h * 32) {
#pragma unroll
                    for (int mt = 0; mt < 2; mt++)
#pragma unroll
                        for (int nt = 0; nt < 4; nt++)
#pragma unroll
                            for (int ci = 0; ci < 4; ci++) {
                                int m = m0 + mt * 16 + g + ((ci >> 1) * 8);
                                int tl = nt * 8 + tq * 2 + (ci & 1);  // 0..31 local
                                float y = acc[0][mt][nt][ci] + acc[1][mt][nt][ci] +
                                          acc[2][mt][nt][ci];
                                y = fmaxf(y, 0.f);
                                __nv_bfloat16 hh = __float2bfloat16(y);
                                __nv_bfloat16 ll =
                                    __float2bfloat16(y - __bfloat162float(hh));
                                stg[tl * 136 + m] = __bfloat16_as_ushort(hh);
                                stg[4352 + tl * 136 + m] = __bfloat16_as_ushort(ll);
                            }
                }
                if (h == 1 && it + 1 < NITER) {
                    if (it + 2 < NITER) CP_WAIT1();
                    else CP_WAIT0();
                }
                __syncthreads();   // stage visible (+ next iter data on h==1)
#pragma unroll
                for (int i = 0; i < 4; i++) {
                    int idx = i * 256 + tid;   // 1024 uint4 per wave
                    int pl = idx >> 9, rem = idx & 511;
                    int r = rem >> 4, sg = rem & 15;
                    uint4 v = *(const uint4*)(stg + pl * 4352 + r * 136 + sg * 8);
                    *(uint4*)(actout +
                              ((size_t)(n * 2 + pl) * T_LEN + tcb + h * 32 + r) * CH +
                              sg * 8) = v;
                }
                if (h == 0) __syncthreads();  // wave-0 stage reads before wave-1 rewrite
            }
        } else {
            if (it + 1 < NITER) {
                if (it + 2 < NITER) CP_WAIT1();
                else CP_WAIT0();
            }
            __syncthreads();   // next iter's X visible
        }
    }
}

// ---------------- classifier: 128 -> 256, + bias, no relu (256 threads) ----------------
__global__ void __launch_bounds__(256, 1) cls_mma(
    const unsigned short* __restrict__ actin,
    const uint32_t* __restrict__ wc,
    const float* __restrict__ bias,
    float* __restrict__ out) {
    extern __shared__ uint32_t sm[];
    const uint32_t sb = smem_u32(sm);
    const int tid = threadIdx.x;
    const int lane = tid & 31, wid = tid >> 5;
    const int g = lane >> 2, tq = lane & 3;
    const int n = blockIdx.y;
    const int tbase = blockIdx.x * SPAN;
    const int mz = blockIdx.z * 128;
    const int m0 = (wid & 3) * 32;
    const int n0 = (wid >> 2) * 16;

#pragma unroll
    for (int i = 0; i < 16; i++) {
        int idx = i * 256 + tid;
        int row = idx >> 4, seg = idx & 15;
        const uint32_t* src = wc + ((size_t)(row >> 7) * 256 + mz + (row & 127)) * 64 + seg * 4;
        cpa16(sb + (row * 68 + seg * 4) * 4, src, 16);
    }
    CP_COMMIT();

    auto load_x = [&](int c) {
        int buf = c & 1;
        int tcb = tbase + c * CCH;
#pragma unroll
        for (int i = 0; i < 4; i++) {
            int idx = i * 256 + tid;
            int pl = idx >> 9, rem = idx & 511;
            int r = rem >> 4, seg = rem & 15;
            const unsigned short* src =
                actin + ((size_t)(n * 2 + pl) * T_LEN + tcb + r) * CH + seg * 8;
            cpa16(sb + (17408 + buf * 4352 + pl * 2176 + r * 68 + seg * 4) * 4, src, 16);
        }
        CP_COMMIT();
    };
    load_x(0);
    load_x(1);
    CP_WAIT1();
    __syncthreads();

    float* stg = (float*)(sm + 26112);

#pragma unroll 1
    for (int c = 0; c < CNCH; c++) {
        const int buf = c & 1;
        const uint32_t* X = sm + 17408 + buf * 4352;

        float acc[3][2][2][4];
#pragma unroll
        for (int p = 0; p < 3; p++)
#pragma unroll
            for (int mt = 0; mt < 2; mt++)
#pragma unroll
                for (int nt = 0; nt < 2; nt++)
#pragma unroll
                    for (int j = 0; j < 4; j++) acc[p][mt][nt][j] = 0.f;

        const uint32_t* Wh = sm;
        const uint32_t* Wl = sm + 8704;
        const uint32_t* Xh = X;
        const uint32_t* Xl = X + 2176;
#pragma unroll
        for (int ks = 0; ks < 8; ks++) {
            uint32_t ah[2][4], al[2][4];
            uint32_t bh0[2], bh1[2], bl0[2], bl1[2];
#pragma unroll
            for (int mt = 0; mt < 2; mt++) {
                int r0 = (m0 + mt * 16 + g) * 68, r1 = (m0 + mt * 16 + g + 8) * 68;
                ah[mt][0] = Wh[r0 + ks * 8 + tq];
                ah[mt][1] = Wh[r1 + ks * 8 + tq];
                ah[mt][2] = Wh[r0 + ks * 8 + 4 + tq];
                ah[mt][3] = Wh[r1 + ks * 8 + 4 + tq];
                al[mt][0] = Wl[r0 + ks * 8 + tq];
                al[mt][1] = Wl[r1 + ks * 8 + tq];
                al[mt][2] = Wl[r0 + ks * 8 + 4 + tq];
                al[mt][3] = Wl[r1 + ks * 8 + 4 + tq];
            }
#pragma unroll
            for (int nt = 0; nt < 2; nt++) {
                int xr = (n0 + nt * 8 + g) * 68;
                bh0[nt] = Xh[xr + ks * 8 + tq];
                bh1[nt] = Xh[xr + ks * 8 + 4 + tq];
                bl0[nt] = Xl[xr + ks * 8 + tq];
                bl1[nt] = Xl[xr + ks * 8 + 4 + tq];
            }
#pragma unroll
            for (int mt = 0; mt < 2; mt++)
#pragma unroll
                for (int nt = 0; nt < 2; nt++)
                    mma16816(acc[0][mt][nt], ah[mt], bh0[nt], bh1[nt]);
#pragma unroll
            for (int mt = 0; mt < 2; mt++)
#pragma unroll
                for (int nt = 0; nt < 2; nt++)
                    mma16816(acc[1][mt][nt], ah[mt], bl0[nt], bl1[nt]);
#pragma unroll
            for (int mt = 0; mt < 2; mt++)
#pragma unroll
                for (int nt = 0; nt < 2; nt++)
                    mma16816(acc[2][mt][nt], al[mt], bh0[nt], bh1[nt]);
        }

        __syncthreads();
        if (c + 2 < CNCH) load_x(c + 2);

#pragma unroll
        for (int mt = 0; mt < 2; mt++)
#pragma unroll
            for (int nt = 0; nt < 2; nt++)
#pragma unroll
                for (int ci = 0; ci < 4; ci++) {
                    int m = m0 + mt * 16 + g + ((ci >> 1) * 8);
                    int tl = n0 + nt * 8 + tq * 2 + (ci & 1);
                    float y = acc[0][mt][nt][ci] + acc[1][mt][nt][ci] + acc[2][mt][nt][ci];
                    stg[m * 34 + tl] = y + __ldg(bias + mz + m);
                }

        if (c + 1 < CNCH) {
            if (c + 2 < CNCH) CP_WAIT1();
            else CP_WAIT0();
        }
        __syncthreads();

        const int tcb = tbase + c * CCH;
#pragma unroll
        for (int i = 0; i < 8; i++) {
            int idx = i * 256 + tid;
            int row = idx >> 4, sg = idx & 15;
            float2 v = *(const float2*)(stg + row * 34 + sg * 2);
            *(float2*)(out + ((size_t)n * NCLS + mz + row) * T_LEN + tcb + sg * 2) = v;
        }
    }
}

// ---------------- launch ----------------
extern "C" void kernel_launch(void* const* d_in, const int* in_sizes, int n_in,
                              void* d_out, int out_size) {
    (void)in_sizes; (void)n_in; (void)out_size;
    const float* seq     = (const float*)d_in[0];
    const float* w_first = (const float*)d_in[1];
    const float* w_rest  = (const float*)d_in[2];
    const float* w_cls   = (const float*)d_in[3];
    const float* b_cls   = (const float*)d_in[4];
    float* out = (float*)d_out;

    unsigned short *a0, *a1;
    uint32_t *whi, *wlo, *wc;
    cudaGetSymbolAddress((void**)&a0, g_act0);
    cudaGetSymbolAddress((void**)&a1, g_act1);
    cudaGetSymbolAddress((void**)&whi, g_whi);
    cudaGetSymbolAddress((void**)&wlo, g_wlo);
    cudaGetSymbolAddress((void**)&wc, g_wc);

    const int smem_layer = 56576 * 4;  // 226304 B
    const int smem_cls   = 30464 * 4;  // 121856 B
    cudaFuncSetAttribute(layer_mma, cudaFuncAttributeMaxDynamicSharedMemorySize, smem_layer);
    cudaFuncSetAttribute(cls_mma, cudaFuncAttributeMaxDynamicSharedMemorySize, smem_cls);

    prep_kernel<<<(27 * 2 * 128 * 64 + 255) / 256, 256>>>(w_rest, w_cls, whi, wlo, wc);
    layer0_kernel<<<dim3(T_LEN / 128, NB), 256>>>(seq, w_first, a0);

    for (int i = 1; i < 28; i++) {
        int l = i % 14;
        int d = 1 << (l % 10);
        const unsigned short* src = (i & 1) ? a0 : a1;
        unsigned short* dst       = (i & 1) ? a1 : a0;
        layer_mma<<<dim3(NXCTA, NB), 256, smem_layer>>>(
            src, dst, whi + (size_t)(i - 1) * 2 * 128 * 64,
            wlo + (size_t)(i - 1) * 2 * 128 * 64, d);
    }

    cls_mma<<<dim3(NXCTA, NB, 2), 256, smem_cls>>>(a1, wc, b_cls, out);
}

// round 12
// speedup vs baseline: 1.2169x; 1.0085x over previous
#include <cuda_runtime.h>
#include <cuda_fp16.h>
#include <cstdint>

#define T_LEN 64000
#define NB 4
#define CH 128
#define NCLS 256
#define CHUNK 64
#define NCHUNK 4
#define NITER 8                   // (chunk, tap) pairs
#define SPAN 256                  // t per CTA
#define NXCTA (T_LEN / SPAN)      // 250
// classifier
#define CCH 32
#define CNCH 8

// ---------------- static device buffers ----------------
__device__ unsigned short g_act0[(size_t)NB * 2 * T_LEN * CH];
__device__ unsigned short g_act1[(size_t)NB * 2 * T_LEN * CH];
__device__ uint32_t g_whi[27 * 2 * 128 * 64];
__device__ uint32_t g_wlo[27 * 2 * 128 * 64];
__device__ uint32_t g_wc[2 * 256 * 64];

// ---------------- helpers ----------------
__device__ __forceinline__ uint32_t smem_u32(const void* p) {
    uint32_t a;
    asm("{ .reg .u64 t; cvta.to.shared.u64 t, %1; cvt.u32.u64 %0, t; }" : "=r"(a) : "l"(p));
    return a;
}
__device__ __forceinline__ void cpa16(uint32_t dst, const void* src, int sz) {
    asm volatile("cp.async.cg.shared.global [%0], [%1], 16, %2;"
                 :: "r"(dst), "l"(src), "r"(sz) : "memory");
}
#define CP_COMMIT() asm volatile("cp.async.commit_group;" ::: "memory")
#define CP_WAIT1()  asm volatile("cp.async.wait_group 1;" ::: "memory")
#define CP_WAIT0()  asm volatile("cp.async.wait_group 0;" ::: "memory")

// fp16 inputs, fp32 accumulator (main product)
__device__ __forceinline__ void mmaf32(float c[4], const uint32_t a[4],
                                       uint32_t b0, uint32_t b1) {
    asm volatile(
        "mma.sync.aligned.m16n8k16.row.col.f32.f16.f16.f32 "
        "{%0,%1,%2,%3}, {%4,%5,%6,%7}, {%8,%9}, {%0,%1,%2,%3};"
        : "+f"(c[0]), "+f"(c[1]), "+f"(c[2]), "+f"(c[3])
        : "r"(a[0]), "r"(a[1]), "r"(a[2]), "r"(a[3]), "r"(b0), "r"(b1));
}
// fp16 inputs, fp16 accumulator (correction products, 2x issue rate)
__device__ __forceinline__ void mmaf16(uint32_t c[2], const uint32_t a[4],
                                       uint32_t b0, uint32_t b1) {
    asm volatile(
        "mma.sync.aligned.m16n8k16.row.col.f16.f16.f16.f16 "
        "{%0,%1}, {%2,%3,%4,%5}, {%6,%7}, {%0,%1};"
        : "+r"(c[0]), "+r"(c[1])
        : "r"(a[0]), "r"(a[1]), "r"(a[2]), "r"(a[3]), "r"(b0), "r"(b1));
}
__device__ __forceinline__ float h2get(uint32_t reg, int hi) {
    __half2 h = *reinterpret_cast<__half2*>(&reg);
    return hi ? __high2float(h) : __low2float(h);
}

// ---------------- prep: split + pack fp16 weights ----------------
__device__ __forceinline__ uint32_t pack_split(float w0, float w1, int plane) {
    __half h0 = __float2half_rn(w0), h1 = __float2half_rn(w1);
    if (plane == 0)
        return (uint32_t)__half_as_ushort(h0) |
               ((uint32_t)__half_as_ushort(h1) << 16);
    __half l0 = __float2half_rn(w0 - __half2float(h0));
    __half l1 = __float2half_rn(w1 - __half2float(h1));
    return (uint32_t)__half_as_ushort(l0) |
           ((uint32_t)__half_as_ushort(l1) << 16);
}

__global__ void prep_kernel(const float* __restrict__ wrest,
                            const float* __restrict__ wcls,
                            uint32_t* __restrict__ whi,
                            uint32_t* __restrict__ wlo,
                            uint32_t* __restrict__ wc) {
    int idx = blockIdx.x * blockDim.x + threadIdx.x;
    if (idx < 27 * 2 * 128 * 64) {
        int kp = idx & 63;
        int m = (idx >> 6) & 127;
        int tap = (idx >> 13) & 1;
        int L = idx >> 14;
        float w0 = wrest[((L * 128 + m) * 128 + kp * 2) * 2 + tap];
        float w1 = wrest[((L * 128 + m) * 128 + kp * 2 + 1) * 2 + tap];
        whi[idx] = pack_split(w0, w1, 0);
        wlo[idx] = pack_split(w0, w1, 1);
    }
    if (idx < 2 * 256 * 64) {
        int kp = idx & 63;
        int m = (idx >> 6) & 255;
        int pl = idx >> 14;
        float w0 = wcls[m * 128 + kp * 2];
        float w1 = wcls[m * 128 + kp * 2 + 1];
        wc[idx] = pack_split(w0, w1, pl);
    }
}

// ---------------- layer 0 ----------------
__global__ void layer0_kernel(const float* __restrict__ seq,
                              const float* __restrict__ wf,
                              unsigned short* __restrict__ actout) {
    int oc = threadIdx.x & 127;
    int half_ = threadIdx.x >> 7;
    int n = blockIdx.y;
    int t0 = blockIdx.x * 128 + half_ * 64;
    float w0 = wf[oc * 2], w1 = wf[oc * 2 + 1];
    const float* xs = seq + (size_t)n * T_LEN;
    unsigned short* ohi = actout + (size_t)(n * 2 + 0) * T_LEN * CH;
    unsigned short* olo = actout + (size_t)(n * 2 + 1) * T_LEN * CH;
    for (int j = 0; j < 64; j++) {
        int t = t0 + j;
        float x1 = xs[t];
        float x0 = (t >= 1) ? xs[t - 1] : 0.f;
        float y = fmaxf(w0 * x0 + w1 * x1, 0.f);
        __half h = __float2half_rn(y);
        __half l = __float2half_rn(y - __half2float(h));
        ohi[(size_t)t * CH + oc] = __half_as_ushort(h);
        olo[(size_t)t * CH + oc] = __half_as_ushort(l);
    }
}

// ---------------- dilated-conv layer via mma.sync fp16 ----------------
// smem (u32 units):
//   [0, 34816)        W : [pl 2][tap 2][m 128][68]
//   [34816, 52224)    X : [buf 2][pl 2][r 64][68]    (buf = tap parity)
//   [52224, 56576)    stage: u16[2 pl][32 t][136 m]
// chunk = 64 t; 8 warps = 4(m of 32) x 2(n of 32); acc persists across taps.
// Main product in f32 acc; two correction products in f16 acc (2x rate).
__global__ void __launch_bounds__(256, 1) layer_mma(
    const unsigned short* __restrict__ actin,
    unsigned short* __restrict__ actout,
    const uint32_t* __restrict__ whi,
    const uint32_t* __restrict__ wlo, int d) {
    extern __shared__ uint32_t sm[];
    const uint32_t sb = smem_u32(sm);
    const int tid = threadIdx.x;
    const int lane = tid & 31, wid = tid >> 5;
    const int g = lane >> 2, tq = lane & 3;
    const int n = blockIdx.y;
    const int tbase = blockIdx.x * SPAN;
    const int m0 = (wid & 3) * 32;
    const int n0 = (wid >> 2) * 32;

    // ---- group: W (both planes) -> smem
#pragma unroll
    for (int i = 0; i < 32; i++) {
        int idx = i * 256 + tid;
        int row = idx >> 4, seg = idx & 15;   // row = pl*256 + tap*128 + m
        const uint32_t* src = ((row < 256) ? whi : wlo) + (row & 255) * 64 + seg * 4;
        cpa16(sb + (row * 68 + seg * 4) * 4, src, 16);
    }
    CP_COMMIT();

    // ---- per-(chunk,tap) X loader: 2 planes x 64 t
    auto load_xt = [&](int it) {
        int c = it >> 1, tap = it & 1, buf = it & 1;
        int tcb = tbase + c * CHUNK;
#pragma unroll
        for (int i = 0; i < 8; i++) {
            int idx = i * 256 + tid;          // 2048 segs
            int pl = idx >> 10, rem = idx & 1023;
            int r = rem >> 4, seg = rem & 15;
            int t = tcb + r - (tap == 0 ? d : 0);
            const unsigned short* src =
                actin + ((size_t)(n * 2 + pl) * T_LEN + (t < 0 ? 0 : t)) * CH + seg * 8;
            cpa16(sb + (34816 + buf * 8704 + pl * 4352 + r * 68 + seg * 4) * 4,
                  src, t >= 0 ? 16 : 0);
        }
        CP_COMMIT();
    };
    load_xt(0);
    load_xt(1);

    CP_WAIT1();          // W + iter0 complete (iter1 in flight)
    __syncthreads();

    unsigned short* stg = (unsigned short*)(sm + 52224);

    float accf[2][4][4];       // main product hh (f32 acc)
    uint32_t acch[2][2][4][2]; // [hl/lh][mt][nt][2] fp16x2 acc

#pragma unroll 1
    for (int it = 0; it < NITER; it++) {
        const int tap = it & 1, buf = it & 1;
        const uint32_t* Xb = sm + 34816 + buf * 8704;

        if (tap == 0) {
#pragma unroll
            for (int mt = 0; mt < 2; mt++)
#pragma unroll
                for (int nt = 0; nt < 4; nt++) {
#pragma unroll
                    for (int j = 0; j < 4; j++) accf[mt][nt][j] = 0.f;
                    acch[0][mt][nt][0] = 0u; acch[0][mt][nt][1] = 0u;
                    acch[1][mt][nt][0] = 0u; acch[1][mt][nt][1] = 0u;
                }
        }

        const uint32_t* Wh = sm + tap * 8704;
        const uint32_t* Wl = sm + 17408 + tap * 8704;
        const uint32_t* Xh = Xb;
        const uint32_t* Xl = Xb + 4352;
#pragma unroll
        for (int ks = 0; ks < 8; ks++) {
            uint32_t ah[2][4], al[2][4];
            uint32_t bh0[4], bh1[4], bl0[4], bl1[4];
#pragma unroll
            for (int mt = 0; mt < 2; mt++) {
                int r0 = (m0 + mt * 16 + g) * 68, r1 = (m0 + mt * 16 + g + 8) * 68;
                ah[mt][0] = Wh[r0 + ks * 8 + tq];
                ah[mt][1] = Wh[r1 + ks * 8 + tq];
                ah[mt][2] = Wh[r0 + ks * 8 + 4 + tq];
                ah[mt][3] = Wh[r1 + ks * 8 + 4 + tq];
                al[mt][0] = Wl[r0 + ks * 8 + tq];
                al[mt][1] = Wl[r1 + ks * 8 + tq];
                al[mt][2] = Wl[r0 + ks * 8 + 4 + tq];
                al[mt][3] = Wl[r1 + ks * 8 + 4 + tq];
            }
#pragma unroll
            for (int nt = 0; nt < 4; nt++) {
                int xr = (n0 + nt * 8 + g) * 68;
                bh0[nt] = Xh[xr + ks * 8 + tq];
                bh1[nt] = Xh[xr + ks * 8 + 4 + tq];
                bl0[nt] = Xl[xr + ks * 8 + tq];
                bl1[nt] = Xl[xr + ks * 8 + 4 + tq];
            }
            // 8 f32-acc MMAs (main) + 16 f16-acc MMAs (corrections)
#pragma unroll
            for (int mt = 0; mt < 2; mt++)
#pragma unroll
                for (int nt = 0; nt < 4; nt++)
                    mmaf32(accf[mt][nt], ah[mt], bh0[nt], bh1[nt]);
#pragma unroll
            for (int mt = 0; mt < 2; mt++)
#pragma unroll
                for (int nt = 0; nt < 4; nt++)
                    mmaf16(acch[0][mt][nt], ah[mt], bl0[nt], bl1[nt]);
#pragma unroll
            for (int mt = 0; mt < 2; mt++)
#pragma unroll
                for (int nt = 0; nt < 4; nt++)
                    mmaf16(acch[1][mt][nt], al[mt], bh0[nt], bh1[nt]);
        }

        __syncthreads();   // all warps done reading X[buf]; stage reads done

        if (it + 2 < NITER) load_xt(it + 2);

        if (tap == 1) {
            // epilogue for chunk c in two 32-t waves
            const int tcb = tbase + (it >> 1) * CHUNK;
#pragma unroll
            for (int h = 0; h < 2; h++) {
                if (n0 == h * 32) {
#pragma unroll
                    for (int mt = 0; mt < 2; mt++)
#pragma unroll
                        for (int nt = 0; nt < 4; nt++)
#pragma unroll
                            for (int ci = 0; ci < 4; ci++) {
                                int m = m0 + mt * 16 + g + ((ci >> 1) * 8);
                                int tl = nt * 8 + tq * 2 + (ci & 1);  // 0..31 local
                                float y = accf[mt][nt][ci] +
                                          h2get(acch[0][mt][nt][ci >> 1], ci & 1) +
                                          h2get(acch[1][mt][nt][ci >> 1], ci & 1);
                                y = fmaxf(y, 0.f);
                                __half hh = __float2half_rn(y);
                                __half ll = __float2half_rn(y - __half2float(hh));
                                stg[tl * 136 + m] = __half_as_ushort(hh);
                                stg[4352 + tl * 136 + m] = __half_as_ushort(ll);
                            }
                }
                if (h == 1 && it + 1 < NITER) {
                    if (it + 2 < NITER) CP_WAIT1();
                    else CP_WAIT0();
                }
                __syncthreads();   // stage visible (+ next iter data on h==1)
#pragma unroll
                for (int i = 0; i < 4; i++) {
                    int idx = i * 256 + tid;   // 1024 uint4 per wave
                    int pl = idx >> 9, rem = idx & 511;
                    int r = rem >> 4, sg = rem & 15;
                    uint4 v = *(const uint4*)(stg + pl * 4352 + r * 136 + sg * 8);
                    *(uint4*)(actout +
                              ((size_t)(n * 2 + pl) * T_LEN + tcb + h * 32 + r) * CH +
                              sg * 8) = v;
                }
                if (h == 0) __syncthreads();  // wave-0 stage reads before wave-1 rewrite
            }
        } else {
            if (it + 1 < NITER) {
                if (it + 2 < NITER) CP_WAIT1();
                else CP_WAIT0();
            }
            __syncthreads();   // next iter's X visible
        }
    }
}

// ---------------- classifier: 128 -> 256, + bias, no relu (256 threads) ----------------
__global__ void __launch_bounds__(256, 1) cls_mma(
    const unsigned short* __restrict__ actin,
    const uint32_t* __restrict__ wc,
    const float* __restrict__ bias,
    float* __restrict__ out) {
    extern __shared__ uint32_t sm[];
    const uint32_t sb = smem_u32(sm);
    const int tid = threadIdx.x;
    const int lane = tid & 31, wid = tid >> 5;
    const int g = lane >> 2, tq = lane & 3;
    const int n = blockIdx.y;
    const int tbase = blockIdx.x * SPAN;
    const int mz = blockIdx.z * 128;
    const int m0 = (wid & 3) * 32;
    const int n0 = (wid >> 2) * 16;

#pragma unroll
    for (int i = 0; i < 16; i++) {
        int idx = i * 256 + tid;
        int row = idx >> 4, seg = idx & 15;
        const uint32_t* src = wc + ((size_t)(row >> 7) * 256 + mz + (row & 127)) * 64 + seg * 4;
        cpa16(sb + (row * 68 + seg * 4) * 4, src, 16);
    }
    CP_COMMIT();

    auto load_x = [&](int c) {
        int buf = c & 1;
        int tcb = tbase + c * CCH;
#pragma unroll
        for (int i = 0; i < 4; i++) {
            int idx = i * 256 + tid;
            int pl = idx >> 9, rem = idx & 511;
            int r = rem >> 4, seg = rem & 15;
            const unsigned short* src =
                actin + ((size_t)(n * 2 + pl) * T_LEN + tcb + r) * CH + seg * 8;
            cpa16(sb + (17408 + buf * 4352 + pl * 2176 + r * 68 + seg * 4) * 4, src, 16);
        }
        CP_COMMIT();
    };
    load_x(0);
    load_x(1);
    CP_WAIT1();
    __syncthreads();

    float* stg = (float*)(sm + 26112);

#pragma unroll 1
    for (int c = 0; c < CNCH; c++) {
        const int buf = c & 1;
        const uint32_t* X = sm + 17408 + buf * 4352;

        float acc[3][2][2][4];
#pragma unroll
        for (int p = 0; p < 3; p++)
#pragma unroll
            for (int mt = 0; mt < 2; mt++)
#pragma unroll
                for (int nt = 0; nt < 2; nt++)
#pragma unroll
                    for (int j = 0; j < 4; j++) acc[p][mt][nt][j] = 0.f;

        const uint32_t* Wh = sm;
        const uint32_t* Wl = sm + 8704;
        const uint32_t* Xh = X;
        const uint32_t* Xl = X + 2176;
#pragma unroll
        for (int ks = 0; ks < 8; ks++) {
            uint32_t ah[2][4], al[2][4];
            uint32_t bh0[2], bh1[2], bl0[2], bl1[2];
#pragma unroll
            for (int mt = 0; mt < 2; mt++) {
                int r0 = (m0 + mt * 16 + g) * 68, r1 = (m0 + mt * 16 + g + 8) * 68;
                ah[mt][0] = Wh[r0 + ks * 8 + tq];
                ah[mt][1] = Wh[r1 + ks * 8 + tq];
                ah[mt][2] = Wh[r0 + ks * 8 + 4 + tq];
                ah[mt][3] = Wh[r1 + ks * 8 + 4 + tq];
                al[mt][0] = Wl[r0 + ks * 8 + tq];
                al[mt][1] = Wl[r1 + ks * 8 + tq];
                al[mt][2] = Wl[r0 + ks * 8 + 4 + tq];
                al[mt][3] = Wl[r1 + ks * 8 + 4 + tq];
            }
#pragma unroll
            for (int nt = 0; nt < 2; nt++) {
                int xr = (n0 + nt * 8 + g) * 68;
                bh0[nt] = Xh[xr + ks * 8 + tq];
                bh1[nt] = Xh[xr + ks * 8 + 4 + tq];
                bl0[nt] = Xl[xr + ks * 8 + tq];
                bl1[nt] = Xl[xr + ks * 8 + 4 + tq];
            }
#pragma unroll
            for (int mt = 0; mt < 2; mt++)
#pragma unroll
                for (int nt = 0; nt < 2; nt++)
                    mmaf32(acc[0][mt][nt], ah[mt], bh0[nt], bh1[nt]);
#pragma unroll
            for (int mt = 0; mt < 2; mt++)
#pragma unroll
                for (int nt = 0; nt < 2; nt++)
                    mmaf32(acc[1][mt][nt], ah[mt], bl0[nt], bl1[nt]);
#pragma unroll
            for (int mt = 0; mt < 2; mt++)
#pragma unroll
                for (int nt = 0; nt < 2; nt++)
                    mmaf32(acc[2][mt][nt], al[mt], bh0[nt], bh1[nt]);
        }

        __syncthreads();
        if (c + 2 < CNCH) load_x(c + 2);

#pragma unroll
        for (int mt = 0; mt < 2; mt++)
#pragma unroll
            for (int nt = 0; nt < 2; nt++)
#pragma unroll
                for (int ci = 0; ci < 4; ci++) {
                    int m = m0 + mt * 16 + g + ((ci >> 1) * 8);
                    int tl = n0 + nt * 8 + tq * 2 + (ci & 1);
                    float y = acc[0][mt][nt][ci] + acc[1][mt][nt][ci] + acc[2][mt][nt][ci];
                    stg[m * 34 + tl] = y + __ldg(bias + mz + m);
                }

        if (c + 1 < CNCH) {
            if (c + 2 < CNCH) CP_WAIT1();
            else CP_WAIT0();
        }
        __syncthreads();

        const int tcb = tbase + c * CCH;
#pragma unroll
        for (int i = 0; i < 8; i++) {
            int idx = i * 256 + tid;
            int row = idx >> 4, sg = idx & 15;
            float2 v = *(const float2*)(stg + row * 34 + sg * 2);
            *(float2*)(out + ((size_t)n * NCLS + mz + row) * T_LEN + tcb + sg * 2) = v;
        }
    }
}

// ---------------- launch ----------------
extern "C" void kernel_launch(void* const* d_in, const int* in_sizes, int n_in,
                              void* d_out, int out_size) {
    (void)in_sizes; (void)n_in; (void)out_size;
    const float* seq     = (const float*)d_in[0];
    const float* w_first = (const float*)d_in[1];
    const float* w_rest  = (const float*)d_in[2];
    const float* w_cls   = (const float*)d_in[3];
    const float* b_cls   = (const float*)d_in[4];
    float* out = (float*)d_out;

    unsigned short *a0, *a1;
    uint32_t *whi, *wlo, *wc;
    cudaGetSymbolAddress((void**)&a0, g_act0);
    cudaGetSymbolAddress((void**)&a1, g_act1);
    cudaGetSymbolAddress((void**)&whi, g_whi);
    cudaGetSymbolAddress((void**)&wlo, g_wlo);
    cudaGetSymbolAddress((void**)&wc, g_wc);

    const int smem_layer = 56576 * 4;  // 226304 B
    const int smem_cls   = 30464 * 4;  // 121856 B
    cudaFuncSetAttribute(layer_mma, cudaFuncAttributeMaxDynamicSharedMemorySize, smem_layer);
    cudaFuncSetAttribute(cls_mma, cudaFuncAttributeMaxDynamicSharedMemorySize, smem_cls);

    prep_kernel<<<(27 * 2 * 128 * 64 + 255) / 256, 256>>>(w_rest, w_cls, whi, wlo, wc);
    layer0_kernel<<<dim3(T_LEN / 128, NB), 256>>>(seq, w_first, a0);

    for (int i = 1; i < 28; i++) {
        int l = i % 14;
        int d = 1 << (l % 10);
        const unsigned short* src = (i & 1) ? a0 : a1;
        unsigned short* dst       = (i & 1) ? a1 : a0;
        layer_mma<<<dim3(NXCTA, NB), 256, smem_layer>>>(
            src, dst, whi + (size_t)(i - 1) * 2 * 128 * 64,
            wlo + (size_t)(i - 1) * 2 * 128 * 64, d);
    }

    cls_mma<<<dim3(NXCTA, NB, 2), 256, smem_cls>>>(a1, wc, b_cls, out);
}